// round 8
// baseline (speedup 1.0000x reference)
#include <cuda_runtime.h>
#include <cuda_bf16.h>
#include <stdint.h>
#include <math.h>

// Problem shape (fixed by the dataset)
#define TOK 8192          // B*S tokens
#define HDIM 1024         // hidden
#define NEXP 8            // experts
#define IDIM 4096         // intermediate
#define NASSIGN (TOK*2)   // top-2 assignments

// ---------------- device scratch (no allocations allowed) ----------------
__device__ int   g_counts[NEXP];
__device__ int   g_cursor[NEXP];
__device__ int   g_offset[NEXP];
__device__ int   g_rows[NASSIGN];    // token index per packed slot
__device__ int   g_dest[NASSIGN];    // 2*t + k   (rank within token)
__device__ float g_wgt[NASSIGN];     // routing weight per slot
__device__ int   g_tope[NASSIGN];    // per token: 2 expert ids
__device__ float g_topw[NASSIGN];    // per token: 2 weights
__device__ float g_hbuf[(size_t)NASSIGN * IDIM];  // 268 MB
__device__ float g_ybuf[(size_t)NASSIGN * HDIM];  // 67 MB

// ---------------- packed f32x2 helpers (B300 FFMA2) ----------------
__device__ __forceinline__ void upk(unsigned long long v, float& lo, float& hi) {
    asm("mov.b64 {%0, %1}, %2;" : "=f"(lo), "=f"(hi) : "l"(v));
}
__device__ __forceinline__ void fma2(unsigned long long& c,
                                     unsigned long long a,
                                     unsigned long long b) {
    asm("fma.rn.f32x2 %0, %1, %2, %0;" : "+l"(c) : "l"(a), "l"(b));
}

// ---------------- init ----------------
__global__ void init_kernel() {
    int i = threadIdx.x;
    if (i < NEXP) { g_counts[i] = 0; g_cursor[i] = 0; }
}

// ---------------- gating: one warp per token ----------------
__global__ void gate_kernel(const float* __restrict__ x,
                            const float* __restrict__ gw) {
    int warp = (blockIdx.x * blockDim.x + threadIdx.x) >> 5;
    int lane = threadIdx.x & 31;
    if (warp >= TOK) return;
    const float* xr = x + (size_t)warp * HDIM;
    float acc[NEXP];
#pragma unroll
    for (int e = 0; e < NEXP; e++) acc[e] = 0.f;
    for (int h = lane; h < HDIM; h += 32) {
        float xv = xr[h];
        const float* g = gw + (size_t)h * NEXP;
#pragma unroll
        for (int e = 0; e < NEXP; e++) acc[e] = fmaf(xv, g[e], acc[e]);
    }
#pragma unroll
    for (int e = 0; e < NEXP; e++) {
#pragma unroll
        for (int off = 16; off > 0; off >>= 1)
            acc[e] += __shfl_xor_sync(0xffffffffu, acc[e], off);
    }
    if (lane == 0) {
        int e0 = 0; float v0 = acc[0];
#pragma unroll
        for (int e = 1; e < NEXP; e++) if (acc[e] > v0) { v0 = acc[e]; e0 = e; }
        int e1 = -1; float v1 = -1e30f;
#pragma unroll
        for (int e = 0; e < NEXP; e++)
            if (e != e0 && acc[e] > v1) { v1 = acc[e]; e1 = e; }
        float p1 = expf(v1 - v0);
        float s  = 1.f + p1;
        float w0 = 1.f / s;
        float w1 = p1 / s;
        int t = warp;
        g_tope[2*t]   = e0;  g_topw[2*t]   = w0;
        g_tope[2*t+1] = e1;  g_topw[2*t+1] = w1;
        atomicAdd(&g_counts[e0], 1);
        atomicAdd(&g_counts[e1], 1);
    }
}

// ---------------- exclusive scan over 8 counts ----------------
__global__ void scan_kernel() {
    int s = 0;
    for (int e = 0; e < NEXP; e++) {
        g_offset[e] = s;
        s += g_counts[e];
        g_cursor[e] = 0;
    }
}

// ---------------- compaction ----------------
__global__ void fill_kernel() {
    int t = blockIdx.x * blockDim.x + threadIdx.x;
    if (t >= TOK) return;
#pragma unroll
    for (int k = 0; k < 2; k++) {
        int e = g_tope[2*t + k];
        int slot = g_offset[e] + atomicAdd(&g_cursor[e], 1);
        g_rows[slot] = t;
        g_dest[slot] = 2*t + k;
        g_wgt[slot]  = g_topw[2*t + k];
    }
}

// ---------------- GEMM1: h = silu(X@w1) * (X@w3), gathered rows ----------
// tile: BM=128, BN=64, BK=16, 256 threads, 8x4 per thread.
// B stored DUPLICATED in smem so LDS.128 yields (b,b) packed broadcast pairs;
// A loaded as ulonglong2 so LDS.128 yields M-row pairs. Zero packing MOVs.
__global__ __launch_bounds__(256) void gemm1_kernel(
    const float* __restrict__ x,
    const float* __restrict__ w1,
    const float* __restrict__ w3) {
    int e = blockIdx.z;
    int count = g_counts[e];
    int mbase = blockIdx.y * 128;
    if (mbase >= count) return;
    int off   = g_offset[e];
    int nbase = blockIdx.x * 64;
    const float* B1 = w1 + (size_t)e * HDIM * IDIM;
    const float* B3 = w3 + (size_t)e * HDIM * IDIM;

    __shared__ __align__(16) float As [16][128];
    __shared__ __align__(16) float Bs1[16][128];   // duplicated pairs
    __shared__ __align__(16) float Bs3[16][128];   // duplicated pairs

    int tid  = threadIdx.x;
    int arow = tid >> 1;            // 0..127
    int aq0  = (tid & 1) * 2;       // quad base 0 or 2
    int rclamp = mbase + arow; if (rclamp >= count) rclamp = count - 1;
    const float* arow_ptr = x + (size_t)g_rows[off + rclamp] * HDIM;

    int bk = tid >> 4;              // 0..15 (k within tile)
    int bn = (tid & 15) * 4;        // source col quad

    int tm = (tid >> 4) * 8;        // output rows tm..tm+7
    int tn = (tid & 15) * 4;        // output cols tn..tn+3

    unsigned long long c1p[4][4], c3p[4][4];
#pragma unroll
    for (int i = 0; i < 4; i++)
#pragma unroll
        for (int j = 0; j < 4; j++) { c1p[i][j] = 0ull; c3p[i][j] = 0ull; }

    for (int k0 = 0; k0 < HDIM; k0 += 16) {
        float4 a0 = *(const float4*)(arow_ptr + k0 + aq0 * 4);
        float4 a1 = *(const float4*)(arow_ptr + k0 + aq0 * 4 + 4);
        As[aq0*4+0][arow] = a0.x; As[aq0*4+1][arow] = a0.y;
        As[aq0*4+2][arow] = a0.z; As[aq0*4+3][arow] = a0.w;
        As[aq0*4+4][arow] = a1.x; As[aq0*4+5][arow] = a1.y;
        As[aq0*4+6][arow] = a1.z; As[aq0*4+7][arow] = a1.w;
        float4 b1 = *(const float4*)(B1 + (size_t)(k0 + bk) * IDIM + nbase + bn);
        float4 b3 = *(const float4*)(B3 + (size_t)(k0 + bk) * IDIM + nbase + bn);
        // duplicated stores: (x,x,y,y) and (z,z,w,w)
        *(float4*)&Bs1[bk][2*bn]     = make_float4(b1.x, b1.x, b1.y, b1.y);
        *(float4*)&Bs1[bk][2*bn + 4] = make_float4(b1.z, b1.z, b1.w, b1.w);
        *(float4*)&Bs3[bk][2*bn]     = make_float4(b3.x, b3.x, b3.y, b3.y);
        *(float4*)&Bs3[bk][2*bn + 4] = make_float4(b3.z, b3.z, b3.w, b3.w);
        __syncthreads();
#pragma unroll
        for (int kk = 0; kk < 16; kk++) {
            ulonglong2 av0 = *(const ulonglong2*)&As[kk][tm];       // pairs (m0,m1),(m2,m3)
            ulonglong2 av1 = *(const ulonglong2*)&As[kk][tm + 4];   // pairs (m4,m5),(m6,m7)
            ulonglong2 b1a = *(const ulonglong2*)&Bs1[kk][2*tn];    // (b0,b0),(b1,b1)
            ulonglong2 b1b = *(const ulonglong2*)&Bs1[kk][2*tn + 4];// (b2,b2),(b3,b3)
            ulonglong2 b3a = *(const ulonglong2*)&Bs3[kk][2*tn];
            ulonglong2 b3b = *(const ulonglong2*)&Bs3[kk][2*tn + 4];
            unsigned long long ap[4] = { av0.x, av0.y, av1.x, av1.y };
            unsigned long long bp1[4] = { b1a.x, b1a.y, b1b.x, b1b.y };
            unsigned long long bp3[4] = { b3a.x, b3a.y, b3b.x, b3b.y };
#pragma unroll
            for (int i2 = 0; i2 < 4; i2++) {
#pragma unroll
                for (int j = 0; j < 4; j++) {
                    fma2(c1p[i2][j], ap[i2], bp1[j]);
                    fma2(c3p[i2][j], ap[i2], bp3[j]);
                }
            }
        }
        __syncthreads();
    }
#pragma unroll
    for (int i2 = 0; i2 < 4; i2++) {
        float c1lo[4], c1hi[4], c3lo[4], c3hi[4];
#pragma unroll
        for (int j = 0; j < 4; j++) {
            upk(c1p[i2][j], c1lo[j], c1hi[j]);
            upk(c3p[i2][j], c3lo[j], c3hi[j]);
        }
        int r0 = mbase + tm + 2 * i2;
        if (r0 < count) {
            float* dst = g_hbuf + (size_t)(off + r0) * IDIM + nbase + tn;
            float4 o; float z;
            z = c1lo[0]; o.x = (z / (1.f + expf(-z))) * c3lo[0];
            z = c1lo[1]; o.y = (z / (1.f + expf(-z))) * c3lo[1];
            z = c1lo[2]; o.z = (z / (1.f + expf(-z))) * c3lo[2];
            z = c1lo[3]; o.w = (z / (1.f + expf(-z))) * c3lo[3];
            *(float4*)dst = o;
        }
        if (r0 + 1 < count) {
            float* dst = g_hbuf + (size_t)(off + r0 + 1) * IDIM + nbase + tn;
            float4 o; float z;
            z = c1hi[0]; o.x = (z / (1.f + expf(-z))) * c3hi[0];
            z = c1hi[1]; o.y = (z / (1.f + expf(-z))) * c3hi[1];
            z = c1hi[2]; o.z = (z / (1.f + expf(-z))) * c3hi[2];
            z = c1hi[3]; o.w = (z / (1.f + expf(-z))) * c3hi[3];
            *(float4*)dst = o;
        }
    }
}

// ---------------- GEMM2: y = h @ w2, scaled scatter to ybuf -------------
__global__ __launch_bounds__(256) void gemm2_kernel(const float* __restrict__ w2) {
    int e = blockIdx.z;
    int count = g_counts[e];
    int mbase = blockIdx.y * 128;
    if (mbase >= count) return;
    int off   = g_offset[e];
    int nbase = blockIdx.x * 64;
    const float* B2 = w2 + (size_t)e * IDIM * HDIM;

    __shared__ __align__(16) float As[16][128];
    __shared__ __align__(16) float Bs[16][128];    // duplicated pairs

    int tid  = threadIdx.x;
    int arow = tid >> 1;
    int aq0  = (tid & 1) * 2;
    int rclamp = mbase + arow; if (rclamp >= count) rclamp = count - 1;
    const float* arow_ptr = g_hbuf + (size_t)(off + rclamp) * IDIM;

    int bk = tid >> 4;
    int bn = (tid & 15) * 4;
    int tm = (tid >> 4) * 8;
    int tn = (tid & 15) * 4;

    unsigned long long cp[4][4];
#pragma unroll
    for (int i = 0; i < 4; i++)
#pragma unroll
        for (int j = 0; j < 4; j++) cp[i][j] = 0ull;

    for (int k0 = 0; k0 < IDIM; k0 += 16) {
        float4 a0 = *(const float4*)(arow_ptr + k0 + aq0 * 4);
        float4 a1 = *(const float4*)(arow_ptr + k0 + aq0 * 4 + 4);
        As[aq0*4+0][arow] = a0.x; As[aq0*4+1][arow] = a0.y;
        As[aq0*4+2][arow] = a0.z; As[aq0*4+3][arow] = a0.w;
        As[aq0*4+4][arow] = a1.x; As[aq0*4+5][arow] = a1.y;
        As[aq0*4+6][arow] = a1.z; As[aq0*4+7][arow] = a1.w;
        float4 b = *(const float4*)(B2 + (size_t)(k0 + bk) * HDIM + nbase + bn);
        *(float4*)&Bs[bk][2*bn]     = make_float4(b.x, b.x, b.y, b.y);
        *(float4*)&Bs[bk][2*bn + 4] = make_float4(b.z, b.z, b.w, b.w);
        __syncthreads();
#pragma unroll
        for (int kk = 0; kk < 16; kk++) {
            ulonglong2 av0 = *(const ulonglong2*)&As[kk][tm];
            ulonglong2 av1 = *(const ulonglong2*)&As[kk][tm + 4];
            ulonglong2 ba  = *(const ulonglong2*)&Bs[kk][2*tn];
            ulonglong2 bb  = *(const ulonglong2*)&Bs[kk][2*tn + 4];
            unsigned long long ap[4] = { av0.x, av0.y, av1.x, av1.y };
            unsigned long long bp2[4] = { ba.x, ba.y, bb.x, bb.y };
#pragma unroll
            for (int i2 = 0; i2 < 4; i2++) {
#pragma unroll
                for (int j = 0; j < 4; j++)
                    fma2(cp[i2][j], ap[i2], bp2[j]);
            }
        }
        __syncthreads();
    }
#pragma unroll
    for (int i2 = 0; i2 < 4; i2++) {
        float clo[4], chi[4];
#pragma unroll
        for (int j = 0; j < 4; j++) upk(cp[i2][j], clo[j], chi[j]);
        int r0 = mbase + tm + 2 * i2;
        if (r0 < count) {
            int slot = off + r0;
            float w = g_wgt[slot];
            int   d = g_dest[slot];
            float4 o = { w * clo[0], w * clo[1], w * clo[2], w * clo[3] };
            *(float4*)(g_ybuf + (size_t)d * HDIM + nbase + tn) = o;
        }
        if (r0 + 1 < count) {
            int slot = off + r0 + 1;
            float w = g_wgt[slot];
            int   d = g_dest[slot];
            float4 o = { w * chi[0], w * chi[1], w * chi[2], w * chi[3] };
            *(float4*)(g_ybuf + (size_t)d * HDIM + nbase + tn) = o;
        }
    }
}

// ---------------- combine: out[t] = y[2t] + y[2t+1] ----------------
__global__ void combine_kernel(float* __restrict__ out) {
    const int W = HDIM / 4;
    int i = blockIdx.x * blockDim.x + threadIdx.x;   // float4 index
    if (i >= TOK * W) return;
    int t = i / W, col = i % W;
    const float4* y = (const float4*)g_ybuf;
    float4 a = y[(size_t)(2 * t) * W + col];
    float4 b = y[(size_t)(2 * t + 1) * W + col];
    float4 o = { a.x + b.x, a.y + b.y, a.z + b.z, a.w + b.w };
    ((float4*)out)[i] = o;
}

// ---------------- launch ----------------
extern "C" void kernel_launch(void* const* d_in, const int* in_sizes, int n_in,
                              void* d_out, int out_size) {
    const float* x  = (const float*)d_in[0];   // [T, H]
    const float* gw = (const float*)d_in[1];   // [H, E]
    const float* w1 = (const float*)d_in[2];   // [E, H, I]
    const float* w3 = (const float*)d_in[3];   // [E, H, I]
    const float* w2 = (const float*)d_in[4];   // [E, I, H]
    float* out = (float*)d_out;                // [T, H]

    init_kernel<<<1, 32>>>();
    gate_kernel<<<TOK / 8, 256>>>(x, gw);      // 8 warps per block
    scan_kernel<<<1, 1>>>();
    fill_kernel<<<TOK / 256, 256>>>();

    dim3 g1(IDIM / 64, TOK / 128, NEXP);
    gemm1_kernel<<<g1, 256>>>(x, w1, w3);

    dim3 g2(HDIM / 64, TOK / 128, NEXP);
    gemm2_kernel<<<g2, 256>>>(w2);

    combine_kernel<<<(TOK * (HDIM / 4)) / 256, 256>>>(out);
}

// round 9
// speedup vs baseline: 1.4551x; 1.4551x over previous
#include <cuda_runtime.h>
#include <cuda_bf16.h>
#include <stdint.h>
#include <math.h>

// Problem shape (fixed by the dataset)
#define TOK 8192          // B*S tokens
#define HDIM 1024         // hidden
#define NEXP 8            // experts
#define IDIM 4096         // intermediate
#define NASSIGN (TOK*2)   // top-2 assignments

// ---------------- device scratch (no allocations allowed) ----------------
__device__ int   g_counts[NEXP];
__device__ int   g_cursor[NEXP];
__device__ int   g_offset[NEXP];
__device__ int   g_rows[NASSIGN];    // token index per packed slot
__device__ int   g_dest[NASSIGN];    // 2*t + k   (rank within token)
__device__ float g_wgt[NASSIGN];     // routing weight per slot
__device__ int   g_tope[NASSIGN];    // per token: 2 expert ids
__device__ float g_topw[NASSIGN];    // per token: 2 weights
__device__ float g_hbuf[(size_t)NASSIGN * IDIM];  // 268 MB
__device__ float g_ybuf[(size_t)NASSIGN * HDIM];  // 67 MB

// ---------------- packed f32x2 helpers (B300 FFMA2) ----------------
__device__ __forceinline__ void upk(unsigned long long v, float& lo, float& hi) {
    asm("mov.b64 {%0, %1}, %2;" : "=f"(lo), "=f"(hi) : "l"(v));
}
__device__ __forceinline__ void fma2(unsigned long long& c,
                                     unsigned long long a,
                                     unsigned long long b) {
    asm("fma.rn.f32x2 %0, %1, %2, %0;" : "+l"(c) : "l"(a), "l"(b));
}

// ---------------- init ----------------
__global__ void init_kernel() {
    int i = threadIdx.x;
    if (i < NEXP) { g_counts[i] = 0; g_cursor[i] = 0; }
}

// ---------------- gating: one warp per token ----------------
__global__ void gate_kernel(const float* __restrict__ x,
                            const float* __restrict__ gw) {
    int warp = (blockIdx.x * blockDim.x + threadIdx.x) >> 5;
    int lane = threadIdx.x & 31;
    if (warp >= TOK) return;
    const float* xr = x + (size_t)warp * HDIM;
    float acc[NEXP];
#pragma unroll
    for (int e = 0; e < NEXP; e++) acc[e] = 0.f;
    for (int h = lane; h < HDIM; h += 32) {
        float xv = xr[h];
        const float* g = gw + (size_t)h * NEXP;
#pragma unroll
        for (int e = 0; e < NEXP; e++) acc[e] = fmaf(xv, g[e], acc[e]);
    }
#pragma unroll
    for (int e = 0; e < NEXP; e++) {
#pragma unroll
        for (int off = 16; off > 0; off >>= 1)
            acc[e] += __shfl_xor_sync(0xffffffffu, acc[e], off);
    }
    if (lane == 0) {
        int e0 = 0; float v0 = acc[0];
#pragma unroll
        for (int e = 1; e < NEXP; e++) if (acc[e] > v0) { v0 = acc[e]; e0 = e; }
        int e1 = -1; float v1 = -1e30f;
#pragma unroll
        for (int e = 0; e < NEXP; e++)
            if (e != e0 && acc[e] > v1) { v1 = acc[e]; e1 = e; }
        float p1 = expf(v1 - v0);
        float s  = 1.f + p1;
        float w0 = 1.f / s;
        float w1 = p1 / s;
        int t = warp;
        g_tope[2*t]   = e0;  g_topw[2*t]   = w0;
        g_tope[2*t+1] = e1;  g_topw[2*t+1] = w1;
        atomicAdd(&g_counts[e0], 1);
        atomicAdd(&g_counts[e1], 1);
    }
}

// ---------------- exclusive scan over 8 counts ----------------
__global__ void scan_kernel() {
    int s = 0;
    for (int e = 0; e < NEXP; e++) {
        g_offset[e] = s;
        s += g_counts[e];
        g_cursor[e] = 0;
    }
}

// ---------------- compaction ----------------
__global__ void fill_kernel() {
    int t = blockIdx.x * blockDim.x + threadIdx.x;
    if (t >= TOK) return;
#pragma unroll
    for (int k = 0; k < 2; k++) {
        int e = g_tope[2*t + k];
        int slot = g_offset[e] + atomicAdd(&g_cursor[e], 1);
        g_rows[slot] = t;
        g_dest[slot] = 2*t + k;
        g_wgt[slot]  = g_topw[2*t + k];
    }
}

// ---------------- GEMM1: h = silu(X@w1) * (X@w3), gathered rows ----------
// tile: BM=128, BN=64, BK=16, 256 threads, 8x4 per thread.
// N-packed FFMA2: B pairs come directly from normal Bs LDS.128 (round-1 bank
// pattern); A duplicated in smem so (a,a) pairs are broadcast LDS.128.
__global__ __launch_bounds__(256) void gemm1_kernel(
    const float* __restrict__ x,
    const float* __restrict__ w1,
    const float* __restrict__ w3) {
    int e = blockIdx.z;
    int count = g_counts[e];
    int mbase = blockIdx.y * 128;
    if (mbase >= count) return;
    int off   = g_offset[e];
    int nbase = blockIdx.x * 64;
    const float* B1 = w1 + (size_t)e * HDIM * IDIM;
    const float* B3 = w3 + (size_t)e * HDIM * IDIM;

    __shared__ __align__(16) float Asd[16][256];   // duplicated (a,a) pairs
    __shared__ __align__(16) float Bs1[16][64];
    __shared__ __align__(16) float Bs3[16][64];

    int tid  = threadIdx.x;
    int arow = tid >> 1;            // 0..127
    int aq0  = (tid & 1) * 2;       // quad base 0 or 2
    int rclamp = mbase + arow; if (rclamp >= count) rclamp = count - 1;
    const float* arow_ptr = x + (size_t)g_rows[off + rclamp] * HDIM;

    int bk = tid >> 4;              // 0..15 (k within tile)
    int bn = (tid & 15) * 4;        // col quad

    int tm = (tid >> 4) * 8;        // output rows tm..tm+7
    int tn = (tid & 15) * 4;        // output cols tn..tn+3

    // N-packed accumulators: cp[i][j2] = (c[i][2j2], c[i][2j2+1])
    unsigned long long c1p[8][2], c3p[8][2];
#pragma unroll
    for (int i = 0; i < 8; i++) {
        c1p[i][0] = 0ull; c1p[i][1] = 0ull;
        c3p[i][0] = 0ull; c3p[i][1] = 0ull;
    }

    for (int k0 = 0; k0 < HDIM; k0 += 16) {
        float4 a0 = *(const float4*)(arow_ptr + k0 + aq0 * 4);
        float4 a1 = *(const float4*)(arow_ptr + k0 + aq0 * 4 + 4);
        int kb = aq0 * 4;
        *(float2*)&Asd[kb+0][2*arow] = make_float2(a0.x, a0.x);
        *(float2*)&Asd[kb+1][2*arow] = make_float2(a0.y, a0.y);
        *(float2*)&Asd[kb+2][2*arow] = make_float2(a0.z, a0.z);
        *(float2*)&Asd[kb+3][2*arow] = make_float2(a0.w, a0.w);
        *(float2*)&Asd[kb+4][2*arow] = make_float2(a1.x, a1.x);
        *(float2*)&Asd[kb+5][2*arow] = make_float2(a1.y, a1.y);
        *(float2*)&Asd[kb+6][2*arow] = make_float2(a1.z, a1.z);
        *(float2*)&Asd[kb+7][2*arow] = make_float2(a1.w, a1.w);
        *(float4*)&Bs1[bk][bn] = *(const float4*)(B1 + (size_t)(k0 + bk) * IDIM + nbase + bn);
        *(float4*)&Bs3[bk][bn] = *(const float4*)(B3 + (size_t)(k0 + bk) * IDIM + nbase + bn);
        __syncthreads();
#pragma unroll
        for (int kk = 0; kk < 16; kk++) {
            ulonglong2 av0 = *(const ulonglong2*)&Asd[kk][2*tm];      // (a0,a0),(a1,a1)
            ulonglong2 av1 = *(const ulonglong2*)&Asd[kk][2*tm + 4];  // (a2,a2),(a3,a3)
            ulonglong2 av2 = *(const ulonglong2*)&Asd[kk][2*tm + 8];
            ulonglong2 av3 = *(const ulonglong2*)&Asd[kk][2*tm + 12];
            ulonglong2 b1 = *(const ulonglong2*)&Bs1[kk][tn];         // (b0,b1),(b2,b3)
            ulonglong2 b3 = *(const ulonglong2*)&Bs3[kk][tn];
            unsigned long long ap[8] = { av0.x, av0.y, av1.x, av1.y,
                                         av2.x, av2.y, av3.x, av3.y };
#pragma unroll
            for (int i = 0; i < 8; i++) {
                fma2(c1p[i][0], ap[i], b1.x);
                fma2(c1p[i][1], ap[i], b1.y);
                fma2(c3p[i][0], ap[i], b3.x);
                fma2(c3p[i][1], ap[i], b3.y);
            }
        }
        __syncthreads();
    }
#pragma unroll
    for (int i = 0; i < 8; i++) {
        int rr = mbase + tm + i;
        if (rr < count) {
            float z0, z1, z2, z3, u0, u1, u2, u3;
            upk(c1p[i][0], z0, z1); upk(c1p[i][1], z2, z3);
            upk(c3p[i][0], u0, u1); upk(c3p[i][1], u2, u3);
            float* dst = g_hbuf + (size_t)(off + rr) * IDIM + nbase + tn;
            float4 o;
            o.x = (z0 / (1.f + expf(-z0))) * u0;
            o.y = (z1 / (1.f + expf(-z1))) * u1;
            o.z = (z2 / (1.f + expf(-z2))) * u2;
            o.w = (z3 / (1.f + expf(-z3))) * u3;
            *(float4*)dst = o;
        }
    }
}

// ---------------- GEMM2: y = h @ w2, scaled scatter to ybuf -------------
__global__ __launch_bounds__(256) void gemm2_kernel(const float* __restrict__ w2) {
    int e = blockIdx.z;
    int count = g_counts[e];
    int mbase = blockIdx.y * 128;
    if (mbase >= count) return;
    int off   = g_offset[e];
    int nbase = blockIdx.x * 64;
    const float* B2 = w2 + (size_t)e * IDIM * HDIM;

    __shared__ __align__(16) float Asd[16][256];
    __shared__ __align__(16) float Bs[16][64];

    int tid  = threadIdx.x;
    int arow = tid >> 1;
    int aq0  = (tid & 1) * 2;
    int rclamp = mbase + arow; if (rclamp >= count) rclamp = count - 1;
    const float* arow_ptr = g_hbuf + (size_t)(off + rclamp) * IDIM;

    int bk = tid >> 4;
    int bn = (tid & 15) * 4;
    int tm = (tid >> 4) * 8;
    int tn = (tid & 15) * 4;

    unsigned long long cp[8][2];
#pragma unroll
    for (int i = 0; i < 8; i++) { cp[i][0] = 0ull; cp[i][1] = 0ull; }

    for (int k0 = 0; k0 < IDIM; k0 += 16) {
        float4 a0 = *(const float4*)(arow_ptr + k0 + aq0 * 4);
        float4 a1 = *(const float4*)(arow_ptr + k0 + aq0 * 4 + 4);
        int kb = aq0 * 4;
        *(float2*)&Asd[kb+0][2*arow] = make_float2(a0.x, a0.x);
        *(float2*)&Asd[kb+1][2*arow] = make_float2(a0.y, a0.y);
        *(float2*)&Asd[kb+2][2*arow] = make_float2(a0.z, a0.z);
        *(float2*)&Asd[kb+3][2*arow] = make_float2(a0.w, a0.w);
        *(float2*)&Asd[kb+4][2*arow] = make_float2(a1.x, a1.x);
        *(float2*)&Asd[kb+5][2*arow] = make_float2(a1.y, a1.y);
        *(float2*)&Asd[kb+6][2*arow] = make_float2(a1.z, a1.z);
        *(float2*)&Asd[kb+7][2*arow] = make_float2(a1.w, a1.w);
        *(float4*)&Bs[bk][bn] = *(const float4*)(B2 + (size_t)(k0 + bk) * HDIM + nbase + bn);
        __syncthreads();
#pragma unroll
        for (int kk = 0; kk < 16; kk++) {
            ulonglong2 av0 = *(const ulonglong2*)&Asd[kk][2*tm];
            ulonglong2 av1 = *(const ulonglong2*)&Asd[kk][2*tm + 4];
            ulonglong2 av2 = *(const ulonglong2*)&Asd[kk][2*tm + 8];
            ulonglong2 av3 = *(const ulonglong2*)&Asd[kk][2*tm + 12];
            ulonglong2 bb = *(const ulonglong2*)&Bs[kk][tn];
            unsigned long long ap[8] = { av0.x, av0.y, av1.x, av1.y,
                                         av2.x, av2.y, av3.x, av3.y };
#pragma unroll
            for (int i = 0; i < 8; i++) {
                fma2(cp[i][0], ap[i], bb.x);
                fma2(cp[i][1], ap[i], bb.y);
            }
        }
        __syncthreads();
    }
#pragma unroll
    for (int i = 0; i < 8; i++) {
        int rr = mbase + tm + i;
        if (rr < count) {
            int slot = off + rr;
            float w = g_wgt[slot];
            int   d = g_dest[slot];
            float c0, c1, c2, c3;
            upk(cp[i][0], c0, c1); upk(cp[i][1], c2, c3);
            float4 o = { w * c0, w * c1, w * c2, w * c3 };
            *(float4*)(g_ybuf + (size_t)d * HDIM + nbase + tn) = o;
        }
    }
}

// ---------------- combine: out[t] = y[2t] + y[2t+1] ----------------
__global__ void combine_kernel(float* __restrict__ out) {
    const int W = HDIM / 4;
    int i = blockIdx.x * blockDim.x + threadIdx.x;   // float4 index
    if (i >= TOK * W) return;
    int t = i / W, col = i % W;
    const float4* y = (const float4*)g_ybuf;
    float4 a = y[(size_t)(2 * t) * W + col];
    float4 b = y[(size_t)(2 * t + 1) * W + col];
    float4 o = { a.x + b.x, a.y + b.y, a.z + b.z, a.w + b.w };
    ((float4*)out)[i] = o;
}

// ---------------- launch ----------------
extern "C" void kernel_launch(void* const* d_in, const int* in_sizes, int n_in,
                              void* d_out, int out_size) {
    const float* x  = (const float*)d_in[0];   // [T, H]
    const float* gw = (const float*)d_in[1];   // [H, E]
    const float* w1 = (const float*)d_in[2];   // [E, H, I]
    const float* w3 = (const float*)d_in[3];   // [E, H, I]
    const float* w2 = (const float*)d_in[4];   // [E, I, H]
    float* out = (float*)d_out;                // [T, H]

    init_kernel<<<1, 32>>>();
    gate_kernel<<<TOK / 8, 256>>>(x, gw);      // 8 warps per block
    scan_kernel<<<1, 1>>>();
    fill_kernel<<<TOK / 256, 256>>>();

    dim3 g1(IDIM / 64, TOK / 128, NEXP);
    gemm1_kernel<<<g1, 256>>>(x, w1, w3);

    dim3 g2(HDIM / 64, TOK / 128, NEXP);
    gemm2_kernel<<<g2, 256>>>(w2);

    combine_kernel<<<(TOK * (HDIM / 4)) / 256, 256>>>(out);
}

// round 10
// speedup vs baseline: 2.8194x; 1.9375x over previous
#include <cuda_runtime.h>
#include <cuda_bf16.h>
#include <stdint.h>
#include <math.h>

// Problem shape (fixed by the dataset)
#define TOK 8192          // B*S tokens
#define HDIM 1024         // hidden
#define NEXP 8            // experts
#define IDIM 4096         // intermediate
#define NASSIGN (TOK*2)   // top-2 assignments

// ------------- device scratch (KEPT <= 335 MB: the passing envelope) -------------
__device__ int   g_counts[NEXP];
__device__ int   g_cursor[NEXP];
__device__ int   g_offset[NEXP];
__device__ int   g_rows[NASSIGN];
__device__ int   g_dest[NASSIGN];
__device__ float g_wgt[NASSIGN];
__device__ int   g_tope[NASSIGN];
__device__ float g_topw[NASSIGN];
__device__ float g_hbuf[(size_t)NASSIGN * IDIM];  // 268 MB
__device__ float g_ybuf[(size_t)NASSIGN * HDIM];  // 67 MB

// ---------------- helpers ----------------
__device__ __forceinline__ uint32_t smem_u32(const void* p) {
    uint32_t a;
    asm("{ .reg .u64 t; cvta.to.shared.u64 t, %1; cvt.u32.u64 %0, t; }" : "=r"(a) : "l"(p));
    return a;
}
__device__ __forceinline__ void ldm4(uint32_t addr, uint32_t* r) {
    asm volatile("ldmatrix.sync.aligned.m8n8.x4.shared.b16 {%0,%1,%2,%3}, [%4];\n"
        : "=r"(r[0]), "=r"(r[1]), "=r"(r[2]), "=r"(r[3]) : "r"(addr));
}
__device__ __forceinline__ void mma_bf16(float* c, const uint32_t* a, uint32_t b0, uint32_t b1) {
    asm volatile(
        "mma.sync.aligned.m16n8k16.row.col.f32.bf16.bf16.f32 "
        "{%0,%1,%2,%3}, {%4,%5,%6,%7}, {%8,%9}, {%0,%1,%2,%3};\n"
        : "+f"(c[0]), "+f"(c[1]), "+f"(c[2]), "+f"(c[3])
        : "r"(a[0]), "r"(a[1]), "r"(a[2]), "r"(a[3]), "r"(b0), "r"(b1));
}
__device__ __forceinline__ uint32_t pack2(__nv_bfloat16 a, __nv_bfloat16 b) {
    __nv_bfloat162 t = __halves2bfloat162(a, b);
    return *reinterpret_cast<uint32_t*>(&t);
}
__device__ __forceinline__ void split32(float f, __nv_bfloat16& h, __nv_bfloat16& l) {
    h = __float2bfloat16_rn(f);
    l = __float2bfloat16_rn(f - __bfloat162float(h));
}

// ---------------- routing kernels (proven) ----------------
__global__ void init_kernel() {
    int i = threadIdx.x;
    if (i < NEXP) { g_counts[i] = 0; g_cursor[i] = 0; }
}

__global__ void gate_kernel(const float* __restrict__ x,
                            const float* __restrict__ gw) {
    int warp = (blockIdx.x * blockDim.x + threadIdx.x) >> 5;
    int lane = threadIdx.x & 31;
    if (warp >= TOK) return;
    const float* xr = x + (size_t)warp * HDIM;
    float acc[NEXP];
#pragma unroll
    for (int e = 0; e < NEXP; e++) acc[e] = 0.f;
    for (int h = lane; h < HDIM; h += 32) {
        float xv = xr[h];
        const float* g = gw + (size_t)h * NEXP;
#pragma unroll
        for (int e = 0; e < NEXP; e++) acc[e] = fmaf(xv, g[e], acc[e]);
    }
#pragma unroll
    for (int e = 0; e < NEXP; e++) {
#pragma unroll
        for (int off = 16; off > 0; off >>= 1)
            acc[e] += __shfl_xor_sync(0xffffffffu, acc[e], off);
    }
    if (lane == 0) {
        int e0 = 0; float v0 = acc[0];
#pragma unroll
        for (int e = 1; e < NEXP; e++) if (acc[e] > v0) { v0 = acc[e]; e0 = e; }
        int e1 = -1; float v1 = -1e30f;
#pragma unroll
        for (int e = 0; e < NEXP; e++)
            if (e != e0 && acc[e] > v1) { v1 = acc[e]; e1 = e; }
        float p1 = expf(v1 - v0);
        float s  = 1.f + p1;
        int t = warp;
        g_tope[2*t]   = e0;  g_topw[2*t]   = 1.f / s;
        g_tope[2*t+1] = e1;  g_topw[2*t+1] = p1 / s;
        atomicAdd(&g_counts[e0], 1);
        atomicAdd(&g_counts[e1], 1);
    }
}

__global__ void scan_kernel() {
    int s = 0;
    for (int e = 0; e < NEXP; e++) {
        g_offset[e] = s;
        s += g_counts[e];
        g_cursor[e] = 0;
    }
}

__global__ void fill_kernel() {
    int t = blockIdx.x * blockDim.x + threadIdx.x;
    if (t >= TOK) return;
#pragma unroll
    for (int k = 0; k < 2; k++) {
        int e = g_tope[2*t + k];
        int slot = g_offset[e] + atomicAdd(&g_cursor[e], 1);
        g_rows[slot] = t;
        g_dest[slot] = 2*t + k;
        g_wgt[slot]  = g_topw[2*t + k];
    }
}

// ======= GEMM1 (mma.sync bf16 hi/lo, on-the-fly conversion): h = silu(X@w1)*(X@w3)
// CTA: M=128 rows x 32 I-cols. B tile: 64 rows (0-31 = w1 cols, 32-63 = w3 cols).
// K-chunk 32. Static smem 30720 B. No persistent bf16 arrays, no transposes.
// SMEM rows are 80 B (32 bf16 padded) -> conflict-free ldmatrix (20-word stride).
__global__ void __launch_bounds__(128) gemm1_kernel(const float* __restrict__ x,
                                                    const float* __restrict__ w1,
                                                    const float* __restrict__ w3) {
    __shared__ __align__(16) uint8_t Ah[128*80], Al[128*80], Bh[64*80], Bl[64*80];
    int e = blockIdx.z;
    int count = g_counts[e];
    int mbase = blockIdx.y * 128;
    if (mbase >= count) return;
    int off  = g_offset[e];
    int nb32 = blockIdx.x * 32;
    int tid = threadIdx.x, lane = tid & 31, wid = tid >> 5;

    uint32_t ah_b = smem_u32(Ah), al_b = smem_u32(Al);
    uint32_t bh_b = smem_u32(Bh), bl_b = smem_u32(Bl);

    // A gather rows: thread covers rows (tid>>3)+16j, float4 slot aq
    int tokr[8];
#pragma unroll
    for (int j = 0; j < 8; j++) {
        int rr = mbase + (tid >> 3) + 16 * j;
        if (rr >= count) rr = count - 1;
        tokr[j] = g_rows[off + rr];
    }
    int aq = tid & 7;

    // B load: thread covers k-rows k2,k2+1 and 4 n-cols n4..n4+3 of each matrix
    int k2 = (tid >> 3) * 2;       // 0..30
    int n4 = (tid & 7) * 4;        // 0..28
    const float* w1p = w1 + (size_t)e * HDIM * IDIM + nb32 + n4;
    const float* w3p = w3 + (size_t)e * HDIM * IDIM + nb32 + n4;

    float zacc[2][4][4], uacc[2][4][4];
#pragma unroll
    for (int m = 0; m < 2; m++)
#pragma unroll
        for (int i = 0; i < 4; i++)
#pragma unroll
            for (int j = 0; j < 4; j++) { zacc[m][i][j] = 0.f; uacc[m][i][j] = 0.f; }

    for (int ch = 0; ch < HDIM / 32; ch++) {
        int kb = ch * 32;
        // ---- A: gather fp32, split hi/lo, store ----
#pragma unroll
        for (int j = 0; j < 8; j++) {
            int r = (tid >> 3) + 16 * j;
            float4 f = *(const float4*)(x + (size_t)tokr[j] * HDIM + kb + aq * 4);
            __nv_bfloat16 h0,h1,h2,h3,l0,l1,l2,l3;
            split32(f.x,h0,l0); split32(f.y,h1,l1);
            split32(f.z,h2,l2); split32(f.w,h3,l3);
            uint2 vh = { pack2(h0,h1), pack2(h2,h3) };
            uint2 vl = { pack2(l0,l1), pack2(l2,l3) };
            uint32_t o = (uint32_t)(r * 80 + (aq >> 1) * 16 + (aq & 1) * 8);
            *(uint2*)(Ah + o) = vh;
            *(uint2*)(Al + o) = vl;
        }
        // ---- B: load fp32 rows (coalesced along n), transpose+split into smem ----
        {
            const float* r0 = w1p + (size_t)(kb + k2) * IDIM;
            float4 f0 = *(const float4*)r0;
            float4 f1 = *(const float4*)(r0 + IDIM);
            float a0[4] = { f0.x, f0.y, f0.z, f0.w };
            float a1[4] = { f1.x, f1.y, f1.z, f1.w };
#pragma unroll
            for (int j = 0; j < 4; j++) {
                __nv_bfloat16 h0,l0,h1,l1;
                split32(a0[j], h0, l0); split32(a1[j], h1, l1);
                uint32_t o = (uint32_t)((n4 + j) * 80 + k2 * 2);
                *(uint32_t*)(Bh + o) = pack2(h0, h1);
                *(uint32_t*)(Bl + o) = pack2(l0, l1);
            }
            const float* r3 = w3p + (size_t)(kb + k2) * IDIM;
            float4 g0 = *(const float4*)r3;
            float4 g1 = *(const float4*)(r3 + IDIM);
            float b0[4] = { g0.x, g0.y, g0.z, g0.w };
            float b1[4] = { g1.x, g1.y, g1.z, g1.w };
#pragma unroll
            for (int j = 0; j < 4; j++) {
                __nv_bfloat16 h0,l0,h1,l1;
                split32(b0[j], h0, l0); split32(b1[j], h1, l1);
                uint32_t o = (uint32_t)((32 + n4 + j) * 80 + k2 * 2);
                *(uint32_t*)(Bh + o) = pack2(h0, h1);
                *(uint32_t*)(Bl + o) = pack2(l0, l1);
            }
        }
        __syncthreads();
        // ---- compute: 2 x k16 steps ----
#pragma unroll
        for (int ks = 0; ks < 2; ks++) {
            int lrow = lane & 15;
            int lk   = ks * 2 + (lane >> 4);
            uint32_t a_h[2][4], a_l[2][4];
#pragma unroll
            for (int mf = 0; mf < 2; mf++) {
                uint32_t aoff = (uint32_t)((wid * 32 + mf * 16 + lrow) * 80 + lk * 16);
                ldm4(ah_b + aoff, a_h[mf]);
                ldm4(al_b + aoff, a_l[mf]);
            }
            int nrow = (lane & 7) + ((lane >> 4) << 3);
            int ck   = ks * 2 + ((lane >> 3) & 1);
#pragma unroll
            for (int g = 0; g < 2; g++) {
#pragma unroll
                for (int b16 = 0; b16 < 2; b16++) {
                    uint32_t boff = (uint32_t)((g * 32 + b16 * 16 + nrow) * 80 + ck * 16);
                    uint32_t b_h[4], b_l[4];
                    ldm4(bh_b + boff, b_h);
                    ldm4(bl_b + boff, b_l);
#pragma unroll
                    for (int mf = 0; mf < 2; mf++) {
#pragma unroll
                        for (int s = 0; s < 2; s++) {
                            float* cc = g ? uacc[mf][b16 * 2 + s] : zacc[mf][b16 * 2 + s];
                            mma_bf16(cc, a_h[mf], b_h[2*s], b_h[2*s+1]);
                            mma_bf16(cc, a_h[mf], b_l[2*s], b_l[2*s+1]);
                            mma_bf16(cc, a_l[mf], b_h[2*s], b_h[2*s+1]);
                        }
                    }
                }
            }
        }
        __syncthreads();
    }

    // ---- epilogue: silu(z)*u straight from registers ----
#pragma unroll
    for (int mf = 0; mf < 2; mf++) {
        int r0 = wid * 32 + mf * 16 + (lane >> 2);
#pragma unroll
        for (int half = 0; half < 2; half++) {
            int rr = mbase + r0 + half * 8;
            if (rr < count) {
                float* dst = g_hbuf + (size_t)(off + rr) * IDIM + nb32 + (lane & 3) * 2;
#pragma unroll
                for (int nb8 = 0; nb8 < 4; nb8++) {
                    float z0 = zacc[mf][nb8][half * 2];
                    float z1 = zacc[mf][nb8][half * 2 + 1];
                    float u0 = uacc[mf][nb8][half * 2];
                    float u1 = uacc[mf][nb8][half * 2 + 1];
                    float2 h;
                    h.x = z0 / (1.f + __expf(-z0)) * u0;
                    h.y = z1 / (1.f + __expf(-z1)) * u1;
                    *(float2*)(dst + nb8 * 8) = h;
                }
            }
        }
    }
}

// ---------------- GEMM2 (round-0 PROVEN SIMT fp32): y = h @ w2 ----------------
__global__ __launch_bounds__(256) void gemm2_kernel(const float* __restrict__ w2) {
    int e = blockIdx.z;
    int count = g_counts[e];
    int mbase = blockIdx.y * 128;
    if (mbase >= count) return;
    int off   = g_offset[e];
    int nbase = blockIdx.x * 64;
    const float* B2 = w2 + (size_t)e * IDIM * HDIM;

    __shared__ float As[16][128];
    __shared__ float Bs[16][64];

    int tid  = threadIdx.x;
    int arow = tid >> 1;
    int aq0  = (tid & 1) * 2;
    int rclamp = mbase + arow; if (rclamp >= count) rclamp = count - 1;
    const float* arow_ptr = g_hbuf + (size_t)(off + rclamp) * IDIM;

    int bk = tid >> 4;
    int bn = (tid & 15) * 4;
    int tm = (tid >> 4) * 8;
    int tn = (tid & 15) * 4;

    float c[8][4];
#pragma unroll
    for (int i = 0; i < 8; i++)
#pragma unroll
        for (int j = 0; j < 4; j++) c[i][j] = 0.f;

    for (int k0 = 0; k0 < IDIM; k0 += 16) {
        float4 a0 = *(const float4*)(arow_ptr + k0 + aq0 * 4);
        float4 a1 = *(const float4*)(arow_ptr + k0 + aq0 * 4 + 4);
        As[aq0*4+0][arow] = a0.x; As[aq0*4+1][arow] = a0.y;
        As[aq0*4+2][arow] = a0.z; As[aq0*4+3][arow] = a0.w;
        As[aq0*4+4][arow] = a1.x; As[aq0*4+5][arow] = a1.y;
        As[aq0*4+6][arow] = a1.z; As[aq0*4+7][arow] = a1.w;
        const float* bp = B2 + (size_t)(k0 + bk) * HDIM + nbase + bn;
        *(float4*)&Bs[bk][bn] = *(const float4*)bp;
        __syncthreads();
#pragma unroll
        for (int kk = 0; kk < 16; kk++) {
            float4 av0 = *(const float4*)&As[kk][tm];
            float4 av1 = *(const float4*)&As[kk][tm + 4];
            float a[8] = {av0.x, av0.y, av0.z, av0.w, av1.x, av1.y, av1.z, av1.w};
            float4 bb = *(const float4*)&Bs[kk][tn];
            float br[4] = {bb.x, bb.y, bb.z, bb.w};
#pragma unroll
            for (int i = 0; i < 8; i++) {
#pragma unroll
                for (int j = 0; j < 4; j++)
                    c[i][j] = fmaf(a[i], br[j], c[i][j]);
            }
        }
        __syncthreads();
    }
#pragma unroll
    for (int i = 0; i < 8; i++) {
        int rr = mbase + tm + i;
        if (rr < count) {
            int slot = off + rr;
            float w = g_wgt[slot];
            int   d = g_dest[slot];
            float4 o = { w * c[i][0], w * c[i][1], w * c[i][2], w * c[i][3] };
            *(float4*)(g_ybuf + (size_t)d * HDIM + nbase + tn) = o;
        }
    }
}

// ---------------- combine ----------------
__global__ void combine_kernel(float* __restrict__ out) {
    const int W = HDIM / 4;
    int i = blockIdx.x * blockDim.x + threadIdx.x;
    if (i >= TOK * W) return;
    int t = i / W, col = i % W;
    const float4* y = (const float4*)g_ybuf;
    float4 a = y[(size_t)(2 * t) * W + col];
    float4 b = y[(size_t)(2 * t + 1) * W + col];
    float4 o = { a.x + b.x, a.y + b.y, a.z + b.z, a.w + b.w };
    ((float4*)out)[i] = o;
}

// ---------------- launch ----------------
extern "C" void kernel_launch(void* const* d_in, const int* in_sizes, int n_in,
                              void* d_out, int out_size) {
    const float* x  = (const float*)d_in[0];   // [T, H]
    const float* gw = (const float*)d_in[1];   // [H, E]
    const float* w1 = (const float*)d_in[2];   // [E, H, I]
    const float* w3 = (const float*)d_in[3];   // [E, H, I]
    const float* w2 = (const float*)d_in[4];   // [E, I, H]
    float* out = (float*)d_out;                // [T, H]

    init_kernel<<<1, 32>>>();
    gate_kernel<<<TOK / 8, 256>>>(x, gw);
    scan_kernel<<<1, 1>>>();
    fill_kernel<<<TOK / 256, 256>>>();

    dim3 g1(IDIM / 32, NASSIGN / 128, NEXP);
    gemm1_kernel<<<g1, 128>>>(x, w1, w3);

    dim3 g2(HDIM / 64, NASSIGN / 128, NEXP);
    gemm2_kernel<<<g2, 256>>>(w2);

    combine_kernel<<<(TOK * (HDIM / 4)) / 256, 256>>>(out);
}

// round 11
// speedup vs baseline: 3.6515x; 1.2951x over previous
#include <cuda_runtime.h>
#include <cuda_bf16.h>
#include <stdint.h>
#include <math.h>

// Problem shape (fixed by the dataset)
#define TOK 8192          // B*S tokens
#define HDIM 1024
#define NEXP 8
#define IDIM 4096
#define NASSIGN (TOK*2)

// ------------- device scratch (KEPT <= 335 MB: the passing envelope) -------------
__device__ int   g_counts[NEXP];
__device__ int   g_cursor[NEXP];
__device__ int   g_offset[NEXP];
__device__ int   g_rows[NASSIGN];
__device__ int   g_dest[NASSIGN];
__device__ float g_wgt[NASSIGN];
__device__ int   g_tope[NASSIGN];
__device__ float g_topw[NASSIGN];
__device__ float g_hbuf[(size_t)NASSIGN * IDIM];  // 268 MB
__device__ float g_ybuf[(size_t)NASSIGN * HDIM];  // 67 MB

// ---------------- helpers ----------------
__device__ __forceinline__ uint32_t smem_u32(const void* p) {
    uint32_t a;
    asm("{ .reg .u64 t; cvta.to.shared.u64 t, %1; cvt.u32.u64 %0, t; }" : "=r"(a) : "l"(p));
    return a;
}
__device__ __forceinline__ void ldm4(uint32_t addr, uint32_t* r) {
    asm volatile("ldmatrix.sync.aligned.m8n8.x4.shared.b16 {%0,%1,%2,%3}, [%4];\n"
        : "=r"(r[0]), "=r"(r[1]), "=r"(r[2]), "=r"(r[3]) : "r"(addr));
}
__device__ __forceinline__ void mma_bf16(float* c, const uint32_t* a, uint32_t b0, uint32_t b1) {
    asm volatile(
        "mma.sync.aligned.m16n8k16.row.col.f32.bf16.bf16.f32 "
        "{%0,%1,%2,%3}, {%4,%5,%6,%7}, {%8,%9}, {%0,%1,%2,%3};\n"
        : "+f"(c[0]), "+f"(c[1]), "+f"(c[2]), "+f"(c[3])
        : "r"(a[0]), "r"(a[1]), "r"(a[2]), "r"(a[3]), "r"(b0), "r"(b1));
}
__device__ __forceinline__ uint32_t pack2(__nv_bfloat16 a, __nv_bfloat16 b) {
    __nv_bfloat162 t = __halves2bfloat162(a, b);
    return *reinterpret_cast<uint32_t*>(&t);
}
__device__ __forceinline__ void split32(float f, __nv_bfloat16& h, __nv_bfloat16& l) {
    h = __float2bfloat16_rn(f);
    l = __float2bfloat16_rn(f - __bfloat162float(h));
}

// ---------------- routing kernels (proven) ----------------
__global__ void init_kernel() {
    int i = threadIdx.x;
    if (i < NEXP) { g_counts[i] = 0; g_cursor[i] = 0; }
}

__global__ void gate_kernel(const float* __restrict__ x,
                            const float* __restrict__ gw) {
    int warp = (blockIdx.x * blockDim.x + threadIdx.x) >> 5;
    int lane = threadIdx.x & 31;
    if (warp >= TOK) return;
    const float* xr = x + (size_t)warp * HDIM;
    float acc[NEXP];
#pragma unroll
    for (int e = 0; e < NEXP; e++) acc[e] = 0.f;
    for (int h = lane; h < HDIM; h += 32) {
        float xv = xr[h];
        const float* g = gw + (size_t)h * NEXP;
#pragma unroll
        for (int e = 0; e < NEXP; e++) acc[e] = fmaf(xv, g[e], acc[e]);
    }
#pragma unroll
    for (int e = 0; e < NEXP; e++) {
#pragma unroll
        for (int off = 16; off > 0; off >>= 1)
            acc[e] += __shfl_xor_sync(0xffffffffu, acc[e], off);
    }
    if (lane == 0) {
        int e0 = 0; float v0 = acc[0];
#pragma unroll
        for (int e = 1; e < NEXP; e++) if (acc[e] > v0) { v0 = acc[e]; e0 = e; }
        int e1 = -1; float v1 = -1e30f;
#pragma unroll
        for (int e = 0; e < NEXP; e++)
            if (e != e0 && acc[e] > v1) { v1 = acc[e]; e1 = e; }
        float p1 = expf(v1 - v0);
        float s  = 1.f + p1;
        int t = warp;
        g_tope[2*t]   = e0;  g_topw[2*t]   = 1.f / s;
        g_tope[2*t+1] = e1;  g_topw[2*t+1] = p1 / s;
        atomicAdd(&g_counts[e0], 1);
        atomicAdd(&g_counts[e1], 1);
    }
}

__global__ void scan_kernel() {
    int s = 0;
    for (int e = 0; e < NEXP; e++) {
        g_offset[e] = s;
        s += g_counts[e];
        g_cursor[e] = 0;
    }
}

__global__ void fill_kernel() {
    int t = blockIdx.x * blockDim.x + threadIdx.x;
    if (t >= TOK) return;
#pragma unroll
    for (int k = 0; k < 2; k++) {
        int e = g_tope[2*t + k];
        int slot = g_offset[e] + atomicAdd(&g_cursor[e], 1);
        g_rows[slot] = t;
        g_dest[slot] = 2*t + k;
        g_wgt[slot]  = g_topw[2*t + k];
    }
}

// ======= GEMM1 (mma.sync bf16 hi/lo, on-the-fly conversion): h = silu(X@w1)*(X@w3)
// (byte-identical to the round-10 PASSING kernel — do not touch)
__global__ void __launch_bounds__(128) gemm1_kernel(const float* __restrict__ x,
                                                    const float* __restrict__ w1,
                                                    const float* __restrict__ w3) {
    __shared__ __align__(16) uint8_t Ah[128*80], Al[128*80], Bh[64*80], Bl[64*80];
    int e = blockIdx.z;
    int count = g_counts[e];
    int mbase = blockIdx.y * 128;
    if (mbase >= count) return;
    int off  = g_offset[e];
    int nb32 = blockIdx.x * 32;
    int tid = threadIdx.x, lane = tid & 31, wid = tid >> 5;

    uint32_t ah_b = smem_u32(Ah), al_b = smem_u32(Al);
    uint32_t bh_b = smem_u32(Bh), bl_b = smem_u32(Bl);

    int tokr[8];
#pragma unroll
    for (int j = 0; j < 8; j++) {
        int rr = mbase + (tid >> 3) + 16 * j;
        if (rr >= count) rr = count - 1;
        tokr[j] = g_rows[off + rr];
    }
    int aq = tid & 7;

    int k2 = (tid >> 3) * 2;
    int n4 = (tid & 7) * 4;
    const float* w1p = w1 + (size_t)e * HDIM * IDIM + nb32 + n4;
    const float* w3p = w3 + (size_t)e * HDIM * IDIM + nb32 + n4;

    float zacc[2][4][4], uacc[2][4][4];
#pragma unroll
    for (int m = 0; m < 2; m++)
#pragma unroll
        for (int i = 0; i < 4; i++)
#pragma unroll
            for (int j = 0; j < 4; j++) { zacc[m][i][j] = 0.f; uacc[m][i][j] = 0.f; }

    for (int ch = 0; ch < HDIM / 32; ch++) {
        int kb = ch * 32;
#pragma unroll
        for (int j = 0; j < 8; j++) {
            int r = (tid >> 3) + 16 * j;
            float4 f = *(const float4*)(x + (size_t)tokr[j] * HDIM + kb + aq * 4);
            __nv_bfloat16 h0,h1,h2,h3,l0,l1,l2,l3;
            split32(f.x,h0,l0); split32(f.y,h1,l1);
            split32(f.z,h2,l2); split32(f.w,h3,l3);
            uint2 vh = { pack2(h0,h1), pack2(h2,h3) };
            uint2 vl = { pack2(l0,l1), pack2(l2,l3) };
            uint32_t o = (uint32_t)(r * 80 + (aq >> 1) * 16 + (aq & 1) * 8);
            *(uint2*)(Ah + o) = vh;
            *(uint2*)(Al + o) = vl;
        }
        {
            const float* r0 = w1p + (size_t)(kb + k2) * IDIM;
            float4 f0 = *(const float4*)r0;
            float4 f1 = *(const float4*)(r0 + IDIM);
            float a0[4] = { f0.x, f0.y, f0.z, f0.w };
            float a1[4] = { f1.x, f1.y, f1.z, f1.w };
#pragma unroll
            for (int j = 0; j < 4; j++) {
                __nv_bfloat16 h0,l0,h1,l1;
                split32(a0[j], h0, l0); split32(a1[j], h1, l1);
                uint32_t o = (uint32_t)((n4 + j) * 80 + k2 * 2);
                *(uint32_t*)(Bh + o) = pack2(h0, h1);
                *(uint32_t*)(Bl + o) = pack2(l0, l1);
            }
            const float* r3 = w3p + (size_t)(kb + k2) * IDIM;
            float4 g0 = *(const float4*)r3;
            float4 g1 = *(const float4*)(r3 + IDIM);
            float b0[4] = { g0.x, g0.y, g0.z, g0.w };
            float b1[4] = { g1.x, g1.y, g1.z, g1.w };
#pragma unroll
            for (int j = 0; j < 4; j++) {
                __nv_bfloat16 h0,l0,h1,l1;
                split32(b0[j], h0, l0); split32(b1[j], h1, l1);
                uint32_t o = (uint32_t)((32 + n4 + j) * 80 + k2 * 2);
                *(uint32_t*)(Bh + o) = pack2(h0, h1);
                *(uint32_t*)(Bl + o) = pack2(l0, l1);
            }
        }
        __syncthreads();
#pragma unroll
        for (int ks = 0; ks < 2; ks++) {
            int lrow = lane & 15;
            int lk   = ks * 2 + (lane >> 4);
            uint32_t a_h[2][4], a_l[2][4];
#pragma unroll
            for (int mf = 0; mf < 2; mf++) {
                uint32_t aoff = (uint32_t)((wid * 32 + mf * 16 + lrow) * 80 + lk * 16);
                ldm4(ah_b + aoff, a_h[mf]);
                ldm4(al_b + aoff, a_l[mf]);
            }
            int nrow = (lane & 7) + ((lane >> 4) << 3);
            int ck   = ks * 2 + ((lane >> 3) & 1);
#pragma unroll
            for (int g = 0; g < 2; g++) {
#pragma unroll
                for (int b16 = 0; b16 < 2; b16++) {
                    uint32_t boff = (uint32_t)((g * 32 + b16 * 16 + nrow) * 80 + ck * 16);
                    uint32_t b_h[4], b_l[4];
                    ldm4(bh_b + boff, b_h);
                    ldm4(bl_b + boff, b_l);
#pragma unroll
                    for (int mf = 0; mf < 2; mf++) {
#pragma unroll
                        for (int s = 0; s < 2; s++) {
                            float* cc = g ? uacc[mf][b16 * 2 + s] : zacc[mf][b16 * 2 + s];
                            mma_bf16(cc, a_h[mf], b_h[2*s], b_h[2*s+1]);
                            mma_bf16(cc, a_h[mf], b_l[2*s], b_l[2*s+1]);
                            mma_bf16(cc, a_l[mf], b_h[2*s], b_h[2*s+1]);
                        }
                    }
                }
            }
        }
        __syncthreads();
    }

#pragma unroll
    for (int mf = 0; mf < 2; mf++) {
        int r0 = wid * 32 + mf * 16 + (lane >> 2);
#pragma unroll
        for (int half = 0; half < 2; half++) {
            int rr = mbase + r0 + half * 8;
            if (rr < count) {
                float* dst = g_hbuf + (size_t)(off + rr) * IDIM + nb32 + (lane & 3) * 2;
#pragma unroll
                for (int nb8 = 0; nb8 < 4; nb8++) {
                    float z0 = zacc[mf][nb8][half * 2];
                    float z1 = zacc[mf][nb8][half * 2 + 1];
                    float u0 = uacc[mf][nb8][half * 2];
                    float u1 = uacc[mf][nb8][half * 2 + 1];
                    float2 h;
                    h.x = z0 / (1.f + __expf(-z0)) * u0;
                    h.y = z1 / (1.f + __expf(-z1)) * u1;
                    *(float2*)(dst + nb8 * 8) = h;
                }
            }
        }
    }
}

// ======= GEMM2 (mma.sync bf16 hi/lo, same proven template): y = h @ w2 ===========
// CTA: M=128 slot-rows x 32 H-cols. B tile 32 rows. K = IDIM, chunks of 32.
// A from g_hbuf fp32 (contiguous slots, clamped), split on the fly.
// B from w2 [E][I][H] rows (N-contiguous), transpose+split — same as gemm1 B.
__global__ void __launch_bounds__(128) gemm2_kernel(const float* __restrict__ w2) {
    __shared__ __align__(16) uint8_t Ah[128*80], Al[128*80], Bh[32*80], Bl[32*80];
    int e = blockIdx.z;
    int count = g_counts[e];
    int mbase = blockIdx.y * 128;
    if (mbase >= count) return;
    int off  = g_offset[e];
    int nb32 = blockIdx.x * 32;
    int tid = threadIdx.x, lane = tid & 31, wid = tid >> 5;

    uint32_t ah_b = smem_u32(Ah), al_b = smem_u32(Al);
    uint32_t bh_b = smem_u32(Bh), bl_b = smem_u32(Bl);

    // A rows: contiguous packed slots (clamped)
    const float* arows[8];
#pragma unroll
    for (int j = 0; j < 8; j++) {
        int rr = mbase + (tid >> 3) + 16 * j;
        if (rr >= count) rr = count - 1;
        arows[j] = g_hbuf + (size_t)(off + rr) * IDIM;
    }
    int aq = tid & 7;

    int k2 = (tid >> 3) * 2;       // 0..30
    int n4 = (tid & 7) * 4;        // 0..28
    const float* w2p = w2 + (size_t)e * IDIM * HDIM + nb32 + n4;

    float acc[2][4][4];
#pragma unroll
    for (int m = 0; m < 2; m++)
#pragma unroll
        for (int i = 0; i < 4; i++)
#pragma unroll
            for (int j = 0; j < 4; j++) acc[m][i][j] = 0.f;

    for (int ch = 0; ch < IDIM / 32; ch++) {
        int kb = ch * 32;
        // ---- A: fp32 h rows, split hi/lo ----
#pragma unroll
        for (int j = 0; j < 8; j++) {
            int r = (tid >> 3) + 16 * j;
            float4 f = *(const float4*)(arows[j] + kb + aq * 4);
            __nv_bfloat16 h0,h1,h2,h3,l0,l1,l2,l3;
            split32(f.x,h0,l0); split32(f.y,h1,l1);
            split32(f.z,h2,l2); split32(f.w,h3,l3);
            uint2 vh = { pack2(h0,h1), pack2(h2,h3) };
            uint2 vl = { pack2(l0,l1), pack2(l2,l3) };
            uint32_t o = (uint32_t)(r * 80 + (aq >> 1) * 16 + (aq & 1) * 8);
            *(uint2*)(Ah + o) = vh;
            *(uint2*)(Al + o) = vl;
        }
        // ---- B: w2 fp32 rows (N-contiguous), transpose+split ----
        {
            const float* r0 = w2p + (size_t)(kb + k2) * HDIM;
            float4 f0 = *(const float4*)r0;
            float4 f1 = *(const float4*)(r0 + HDIM);
            float a0[4] = { f0.x, f0.y, f0.z, f0.w };
            float a1[4] = { f1.x, f1.y, f1.z, f1.w };
#pragma unroll
            for (int j = 0; j < 4; j++) {
                __nv_bfloat16 h0,l0,h1,l1;
                split32(a0[j], h0, l0); split32(a1[j], h1, l1);
                uint32_t o = (uint32_t)((n4 + j) * 80 + k2 * 2);
                *(uint32_t*)(Bh + o) = pack2(h0, h1);
                *(uint32_t*)(Bl + o) = pack2(l0, l1);
            }
        }
        __syncthreads();
        // ---- compute: 2 x k16 ----
#pragma unroll
        for (int ks = 0; ks < 2; ks++) {
            int lrow = lane & 15;
            int lk   = ks * 2 + (lane >> 4);
            uint32_t a_h[2][4], a_l[2][4];
#pragma unroll
            for (int mf = 0; mf < 2; mf++) {
                uint32_t aoff = (uint32_t)((wid * 32 + mf * 16 + lrow) * 80 + lk * 16);
                ldm4(ah_b + aoff, a_h[mf]);
                ldm4(al_b + aoff, a_l[mf]);
            }
            int nrow = (lane & 7) + ((lane >> 4) << 3);
            int ck   = ks * 2 + ((lane >> 3) & 1);
#pragma unroll
            for (int b16 = 0; b16 < 2; b16++) {
                uint32_t boff = (uint32_t)((b16 * 16 + nrow) * 80 + ck * 16);
                uint32_t b_h[4], b_l[4];
                ldm4(bh_b + boff, b_h);
                ldm4(bl_b + boff, b_l);
#pragma unroll
                for (int mf = 0; mf < 2; mf++) {
#pragma unroll
                    for (int s = 0; s < 2; s++) {
                        float* cc = acc[mf][b16 * 2 + s];
                        mma_bf16(cc, a_h[mf], b_h[2*s], b_h[2*s+1]);
                        mma_bf16(cc, a_h[mf], b_l[2*s], b_l[2*s+1]);
                        mma_bf16(cc, a_l[mf], b_h[2*s], b_h[2*s+1]);
                    }
                }
            }
        }
        __syncthreads();
    }

    // ---- epilogue: weight-scale + scatter to ybuf[dest] ----
#pragma unroll
    for (int mf = 0; mf < 2; mf++) {
        int r0 = wid * 32 + mf * 16 + (lane >> 2);
#pragma unroll
        for (int half = 0; half < 2; half++) {
            int rr = mbase + r0 + half * 8;
            if (rr < count) {
                int slot = off + rr;
                float w = g_wgt[slot];
                int   d = g_dest[slot];
                float* dst = g_ybuf + (size_t)d * HDIM + nb32 + (lane & 3) * 2;
#pragma unroll
                for (int nb8 = 0; nb8 < 4; nb8++) {
                    float2 o;
                    o.x = w * acc[mf][nb8][half * 2];
                    o.y = w * acc[mf][nb8][half * 2 + 1];
                    *(float2*)(dst + nb8 * 8) = o;
                }
            }
        }
    }
}

// ---------------- combine ----------------
__global__ void combine_kernel(float* __restrict__ out) {
    const int W = HDIM / 4;
    int i = blockIdx.x * blockDim.x + threadIdx.x;
    if (i >= TOK * W) return;
    int t = i / W, col = i % W;
    const float4* y = (const float4*)g_ybuf;
    float4 a = y[(size_t)(2 * t) * W + col];
    float4 b = y[(size_t)(2 * t + 1) * W + col];
    float4 o = { a.x + b.x, a.y + b.y, a.z + b.z, a.w + b.w };
    ((float4*)out)[i] = o;
}

// ---------------- launch ----------------
extern "C" void kernel_launch(void* const* d_in, const int* in_sizes, int n_in,
                              void* d_out, int out_size) {
    const float* x  = (const float*)d_in[0];   // [T, H]
    const float* gw = (const float*)d_in[1];   // [H, E]
    const float* w1 = (const float*)d_in[2];   // [E, H, I]
    const float* w3 = (const float*)d_in[3];   // [E, H, I]
    const float* w2 = (const float*)d_in[4];   // [E, I, H]
    float* out = (float*)d_out;                // [T, H]

    init_kernel<<<1, 32>>>();
    gate_kernel<<<TOK / 8, 256>>>(x, gw);
    scan_kernel<<<1, 1>>>();
    fill_kernel<<<TOK / 256, 256>>>();

    dim3 g1(IDIM / 32, NASSIGN / 128, NEXP);
    gemm1_kernel<<<g1, 128>>>(x, w1, w3);

    dim3 g2(HDIM / 32, NASSIGN / 128, NEXP);
    gemm2_kernel<<<g2, 128>>>(w2);

    combine_kernel<<<(TOK * (HDIM / 4)) / 256, 256>>>(out);
}